// round 1
// baseline (speedup 1.0000x reference)
#include <cuda_runtime.h>
#include <math.h>

#define LSEQ 32768
#define H 256
#define PP 128
#define CH 128
#define NCH 256
#define NL 4

// ---------------- scratch (static __device__, no allocation) ----------------
__device__ float g_x[LSEQ * H];      // residual stream
__device__ float g_h[LSEQ * H];      // normed input / gelu output
__device__ float g_bu[LSEQ * H];     // Bu, interleaved re/im (L x 2P)
__device__ float g_xs[LSEQ * H];     // scan states, interleaved (L x 2P)
__device__ float g_y[LSEQ * H];      // ssm output
__device__ float g_p[LSEQ * 512];    // GLU pre-activations
__device__ float2 g_e[NCH * PP];     // chunk end states
__device__ float2 g_s[NCH * PP];     // chunk init states
__device__ float g_Wb[NL * H * H];   // folded B_bar weight (K=h, N=2p interleaved)
__device__ float g_Wc[NL * H * H];   // folded C weight (K=2p interleaved, N=h)
__device__ float g_Wg[NL * H * 512]; // W1|W2 concat
__device__ float g_bg[NL * 512];
__device__ float g_WoutP[H * 128];   // W_out zero-padded to 128 cols
__device__ float g_boutP[128];
__device__ float2 g_abar[NL * PP];
__device__ float2 g_apow[NL * PP];   // abar^CH
__device__ float g_x0[H];

// ---------------- setup kernels ----------------
__global__ void k_x0(const float* __restrict__ latent, const float* __restrict__ W,
                     const float* __restrict__ b) {
    int j = threadIdx.x;
    float s = b[j];
    for (int i = 0; i < H; i++) s += latent[i] * W[i * H + j];
    g_x0[j] = s > 0.f ? s : 0.01f * s;  // leaky_relu
}

__global__ void k_fill() {
    int idx = blockIdx.x * blockDim.x + threadIdx.x;  // L*H/4 float4s
    float4 v = ((const float4*)g_x0)[idx & 63];
    ((float4*)g_x)[idx] = v;
}

__global__ void k_prep(const float* __restrict__ Lre, const float* __restrict__ Lim,
                       const float* __restrict__ Bre, const float* __restrict__ Bim,
                       const float* __restrict__ Cre, const float* __restrict__ Cim,
                       const float* __restrict__ lstep) {
    int l = blockIdx.x >> 7;
    int p = blockIdx.x & 127;
    int h = threadIdx.x;
    float step = expf(lstep[l * PP + p]);
    float lr = Lre[l * PP + p], li = Lim[l * PP + p];
    float er = expf(lr * step);
    float sb, cb;
    sincosf(li * step, &sb, &cb);
    float abr = er * cb, abi = er * sb;                 // Lambda_bar
    float den = lr * lr + li * li;
    float nr = abr - 1.f, ni = abi;
    float fr = (nr * lr + ni * li) / den;               // (lam_bar-1)/lam
    float fi = (ni * lr - nr * li) / den;
    float br = Bre[(l * PP + p) * H + h], bi = Bim[(l * PP + p) * H + h];
    g_Wb[l * H * H + h * H + 2 * p]     = fr * br - fi * bi;
    g_Wb[l * H * H + h * H + 2 * p + 1] = fr * bi + fi * br;
    g_Wc[l * H * H + (2 * p) * H + h]     =  2.f * Cre[(l * H + h) * PP + p];
    g_Wc[l * H * H + (2 * p + 1) * H + h] = -2.f * Cim[(l * H + h) * PP + p];
    if (h == 0) {
        g_abar[l * PP + p] = make_float2(abr, abi);
        float er2 = expf(lr * step * (float)CH);
        float sb2, cb2;
        sincosf(li * step * (float)CH, &sb2, &cb2);
        g_apow[l * PP + p] = make_float2(er2 * cb2, er2 * sb2);
    }
}

__global__ void k_wg(const float* __restrict__ W1, const float* __restrict__ b1,
                     const float* __restrict__ W2, const float* __restrict__ b2) {
    int idx = blockIdx.x * blockDim.x + threadIdx.x;  // NL*H*512
    int l = idx / (H * 512);
    int r = idx % (H * 512);
    int i = r / 512, j = r % 512;
    g_Wg[idx] = (j < 256) ? W1[(l * H + i) * H + j] : W2[(l * H + i) * H + (j - 256)];
    if (i == 0) g_bg[l * 512 + j] = (j < 256) ? b1[l * H + j] : b2[l * H + (j - 256)];
}

__global__ void k_wout(const float* __restrict__ Wout, const float* __restrict__ bout) {
    int idx = blockIdx.x * blockDim.x + threadIdx.x;  // H*128
    int i = idx >> 7, j = idx & 127;
    g_WoutP[idx] = (j < 64) ? Wout[i * 64 + j] : 0.f;
    if (i == 0) g_boutP[j] = (j < 64) ? bout[j] : 0.f;
}

// ---------------- layernorm (+optional gelu) ----------------
template <bool GELU>
__global__ void k_ln(const float* __restrict__ x, float* __restrict__ o,
                     const float* __restrict__ sc, const float* __restrict__ bi) {
    int row = blockIdx.x * 4 + (threadIdx.x >> 5);
    int lane = threadIdx.x & 31;
    const float* xr = x + (size_t)row * H;
    float4 a = *(const float4*)(xr + lane * 8);
    float4 b = *(const float4*)(xr + lane * 8 + 4);
    float v[8] = {a.x, a.y, a.z, a.w, b.x, b.y, b.z, b.w};
    float s = 0.f, q = 0.f;
#pragma unroll
    for (int i = 0; i < 8; i++) { s += v[i]; q += v[i] * v[i]; }
#pragma unroll
    for (int off = 16; off; off >>= 1) {
        s += __shfl_xor_sync(0xffffffffu, s, off);
        q += __shfl_xor_sync(0xffffffffu, q, off);
    }
    float mu = s * (1.f / H);
    float var = q * (1.f / H) - mu * mu;
    float r = rsqrtf(var + 1e-6f);
    float out[8];
#pragma unroll
    for (int i = 0; i < 8; i++) {
        int col = lane * 8 + i;
        float t = (v[i] - mu) * r * sc[col] + bi[col];
        if (GELU) {
            float t3 = t * t * t;
            t = 0.5f * t * (1.f + tanhf(0.7978845608028654f * (t + 0.044715f * t3)));
        }
        out[i] = t;
    }
    float* orow = o + (size_t)row * H + lane * 8;
    *(float4*)orow = make_float4(out[0], out[1], out[2], out[3]);
    *(float4*)(orow + 4) = make_float4(out[4], out[5], out[6], out[7]);
}

// ---------------- chunked diagonal complex scan ----------------
__global__ void k_scan1(int l) {
    int c = blockIdx.x, p = threadIdx.x;
    float2 a = g_abar[l * PP + p];
    const float2* bu = (const float2*)g_bu + (size_t)c * CH * PP + p;
    float2 st = make_float2(0.f, 0.f);
#pragma unroll 4
    for (int t = 0; t < CH; t++) {
        float2 b = bu[(size_t)t * PP];
        st = make_float2(a.x * st.x - a.y * st.y + b.x, a.x * st.y + a.y * st.x + b.y);
    }
    g_e[c * PP + p] = st;
}

__global__ void k_carry(int l) {
    int p = threadIdx.x;
    float2 ap = g_apow[l * PP + p];
    float2 cur = make_float2(0.f, 0.f);
    for (int c = 0; c < NCH; c++) {
        g_s[c * PP + p] = cur;
        float2 e = g_e[c * PP + p];
        cur = make_float2(ap.x * cur.x - ap.y * cur.y + e.x, ap.x * cur.y + ap.y * cur.x + e.y);
    }
}

__global__ void k_scan2(int l) {
    int c = blockIdx.x, p = threadIdx.x;
    float2 a = g_abar[l * PP + p];
    const float2* bu = (const float2*)g_bu + (size_t)c * CH * PP + p;
    float2* xo = (float2*)g_xs + (size_t)c * CH * PP + p;
    float2 st = g_s[c * PP + p];
#pragma unroll 4
    for (int t = 0; t < CH; t++) {
        float2 b = bu[(size_t)t * PP];
        st = make_float2(a.x * st.x - a.y * st.y + b.x, a.x * st.y + a.y * st.x + b.y);
        xo[(size_t)t * PP] = st;
    }
}

// ---------------- SGEMM: C[M,N] = A[M,K]@B[K,N] (+bias) (+U*Dv) ----------------
// BM=128, BN=128, BK=16, 256 threads, 8x8 microtile
template <int EPI>
__global__ __launch_bounds__(256) void sgemm(
    const float* __restrict__ A, const float* __restrict__ B,
    const float* __restrict__ bias, float* __restrict__ C,
    int K, int N, int ldc, int ncols,
    const float* __restrict__ U, const float* __restrict__ Dv) {
    __shared__ float As[16][132];
    __shared__ float Bs[16][128];
    int tid = threadIdx.x;
    int bm = blockIdx.y * 128;
    int bn = blockIdx.x * 128;
    int arow = tid >> 1;
    int akk = (tid & 1) * 8;
    int bkrow = tid >> 4;
    int bcol = (tid & 15) * 8;
    int tx = tid & 15, ty = tid >> 4;
    float acc[8][8] = {};
    const float* Aptr = A + (size_t)(bm + arow) * K;
    for (int k0 = 0; k0 < K; k0 += 16) {
        float4 a0 = *(const float4*)(Aptr + k0 + akk);
        float4 a1 = *(const float4*)(Aptr + k0 + akk + 4);
        As[akk + 0][arow] = a0.x; As[akk + 1][arow] = a0.y;
        As[akk + 2][arow] = a0.z; As[akk + 3][arow] = a0.w;
        As[akk + 4][arow] = a1.x; As[akk + 5][arow] = a1.y;
        As[akk + 6][arow] = a1.z; As[akk + 7][arow] = a1.w;
        const float* Bp = B + (size_t)(k0 + bkrow) * N + bn + bcol;
        *(float4*)&Bs[bkrow][bcol] = *(const float4*)Bp;
        *(float4*)&Bs[bkrow][bcol + 4] = *(const float4*)(Bp + 4);
        __syncthreads();
#pragma unroll
        for (int k = 0; k < 16; k++) {
            float ar[8], br[8];
            *(float4*)ar = *(const float4*)&As[k][ty * 8];
            *(float4*)(ar + 4) = *(const float4*)&As[k][ty * 8 + 4];
            *(float4*)br = *(const float4*)&Bs[k][tx * 8];
            *(float4*)(br + 4) = *(const float4*)&Bs[k][tx * 8 + 4];
#pragma unroll
            for (int i = 0; i < 8; i++)
#pragma unroll
                for (int j = 0; j < 8; j++) acc[i][j] += ar[i] * br[j];
        }
        __syncthreads();
    }
#pragma unroll
    for (int i = 0; i < 8; i++) {
        int row = bm + ty * 8 + i;
#pragma unroll
        for (int j = 0; j < 8; j++) {
            int col = bn + tx * 8 + j;
            float c = acc[i][j];
            if (bias) c += bias[col];
            if (EPI == 1) c += U[(size_t)row * H + col] * Dv[col];
            if (col < ncols) C[(size_t)row * ldc + col] = c;
        }
    }
}

// ---------------- GLU combine: x += p1 * sigmoid(p2) ----------------
__global__ void k_glu() {
    int idx = blockIdx.x * blockDim.x + threadIdx.x;  // L*H/4
    int row = idx >> 6;
    int c4 = idx & 63;
    float4 a = *(const float4*)(g_p + (size_t)row * 512 + c4 * 4);
    float4 b = *(const float4*)(g_p + (size_t)row * 512 + 256 + c4 * 4);
    float4 x = ((float4*)g_x)[idx];
    x.x += a.x * (1.f / (1.f + expf(-b.x)));
    x.y += a.y * (1.f / (1.f + expf(-b.y)));
    x.z += a.z * (1.f / (1.f + expf(-b.z)));
    x.w += a.w * (1.f / (1.f + expf(-b.w)));
    ((float4*)g_x)[idx] = x;
}

// ---------------- host launcher ----------------
extern "C" void kernel_launch(void* const* d_in, const int* in_sizes, int n_in,
                              void* d_out, int out_size) {
    const float* latent = (const float*)d_in[0];
    const float* Wexp   = (const float*)d_in[1];
    const float* bexp   = (const float*)d_in[2];
    const float* ns     = (const float*)d_in[3];
    const float* nb     = (const float*)d_in[4];
    const float* Lre    = (const float*)d_in[5];
    const float* Lim    = (const float*)d_in[6];
    const float* Bre    = (const float*)d_in[7];
    const float* Bim    = (const float*)d_in[8];
    const float* Cre    = (const float*)d_in[9];
    const float* Cim    = (const float*)d_in[10];
    const float* Dv     = (const float*)d_in[11];
    const float* lstep  = (const float*)d_in[12];
    const float* W1     = (const float*)d_in[13];
    const float* b1     = (const float*)d_in[14];
    const float* W2     = (const float*)d_in[15];
    const float* b2     = (const float*)d_in[16];
    const float* Wout   = (const float*)d_in[17];
    const float* bout   = (const float*)d_in[18];

    float *px, *ph, *pbu, *pxs, *py, *pp, *pWb, *pWc, *pWg, *pbg, *pWoutP, *pboutP;
    cudaGetSymbolAddress((void**)&px, g_x);
    cudaGetSymbolAddress((void**)&ph, g_h);
    cudaGetSymbolAddress((void**)&pbu, g_bu);
    cudaGetSymbolAddress((void**)&pxs, g_xs);
    cudaGetSymbolAddress((void**)&py, g_y);
    cudaGetSymbolAddress((void**)&pp, g_p);
    cudaGetSymbolAddress((void**)&pWb, g_Wb);
    cudaGetSymbolAddress((void**)&pWc, g_Wc);
    cudaGetSymbolAddress((void**)&pWg, g_Wg);
    cudaGetSymbolAddress((void**)&pbg, g_bg);
    cudaGetSymbolAddress((void**)&pWoutP, g_WoutP);
    cudaGetSymbolAddress((void**)&pboutP, g_boutP);

    k_x0<<<1, 256>>>(latent, Wexp, bexp);
    k_fill<<<(LSEQ * H / 4) / 256, 256>>>();
    k_prep<<<NL * PP, 256>>>(Lre, Lim, Bre, Bim, Cre, Cim, lstep);
    k_wg<<<(NL * H * 512) / 256, 256>>>(W1, b1, W2, b2);
    k_wout<<<(H * 128) / 256, 256>>>(Wout, bout);

    for (int l = 0; l < NL; l++) {
        k_ln<false><<<LSEQ / 4, 128>>>(px, ph, ns + l * H, nb + l * H);
        sgemm<0><<<dim3(2, 256), 256>>>(ph, pWb + l * H * H, nullptr, pbu,
                                        H, H, H, H, nullptr, nullptr);
        k_scan1<<<NCH, PP>>>(l);
        k_carry<<<1, PP>>>(l);
        k_scan2<<<NCH, PP>>>(l);
        sgemm<1><<<dim3(2, 256), 256>>>(pxs, pWc + l * H * H, nullptr, py,
                                        H, H, H, H, ph, Dv + l * H);
        k_ln<true><<<LSEQ / 4, 128>>>(py, ph, ns + l * H, nb + l * H);
        sgemm<0><<<dim3(4, 256), 256>>>(ph, pWg + l * H * 512, pbg + l * 512, pp,
                                        H, 512, 512, 512, nullptr, nullptr);
        k_glu<<<(LSEQ * H / 4) / 256, 256>>>();
    }
    sgemm<0><<<dim3(1, 256), 256>>>(px, pWoutP, pboutP, (float*)d_out,
                                    H, 128, 64, 64, nullptr, nullptr);
}

// round 6
// speedup vs baseline: 2.4487x; 2.4487x over previous
#include <cuda_runtime.h>
#include <cuda_bf16.h>
#include <cstdint>
#include <math.h>

#define LSEQ 32768
#define H 256
#define PP 128
#define CH 128
#define NCH 256
#define NL 4
#define GK 256

// ---------------- scratch (static __device__, no allocation) ----------------
__device__ float g_x[LSEQ * H];            // residual stream (fp32)
__device__ float g_bu[LSEQ * H];           // Bu, interleaved re/im (fp32)
__device__ float g_y[LSEQ * H];            // ssm output (fp32)
__device__ float g_p[LSEQ * 512];          // GLU pre-activations (fp32)
__device__ __nv_bfloat16 g_hh[LSEQ * H];   // ln/gelu output hi
__device__ __nv_bfloat16 g_hl[LSEQ * H];   // ln/gelu output lo
__device__ __nv_bfloat16 g_sh[LSEQ * H];   // scan states / final x hi
__device__ __nv_bfloat16 g_sl[LSEQ * H];   // scan states / final x lo
__device__ float2 g_e[NCH * PP];
__device__ float2 g_s[NCH * PP];
__device__ __nv_bfloat16 g_Wbh[NL * H * H], g_Wbl[NL * H * H];   // [N=2p][K=h]
__device__ __nv_bfloat16 g_Wch[NL * H * H], g_Wcl[NL * H * H];   // [N=h][K=2p]
__device__ __nv_bfloat16 g_Wgh[NL * 512 * H], g_Wgl[NL * 512 * H]; // [N=512][K=256]
__device__ float g_bg[NL * 512];
__device__ __nv_bfloat16 g_Woh[128 * H], g_Wol[128 * H];         // [N=128][K=256]
__device__ float g_boutP[128];
__device__ float2 g_abar[NL * PP];
__device__ float2 g_apow[NL * PP];
__device__ float g_x0[H];

// ---------------- helpers ----------------
__device__ __forceinline__ uint32_t smem_u32(const void* p) {
    uint32_t a;
    asm("{ .reg .u64 t; cvta.to.shared.u64 t, %1; cvt.u32.u64 %0, t; }" : "=r"(a) : "l"(p));
    return a;
}
__device__ __forceinline__ void cpa(uint32_t s, const void* g) {
    asm volatile("cp.async.cg.shared.global [%0], [%1], 16;" :: "r"(s), "l"(g));
}
__device__ __forceinline__ void ldsm4(uint32_t* r, uint32_t a) {
    asm volatile("ldmatrix.sync.aligned.m8n8.x4.shared.b16 {%0,%1,%2,%3}, [%4];"
                 : "=r"(r[0]), "=r"(r[1]), "=r"(r[2]), "=r"(r[3]) : "r"(a));
}
__device__ __forceinline__ void mma16816(float* d, const uint32_t* a, uint32_t b0, uint32_t b1) {
    asm volatile("mma.sync.aligned.m16n8k16.row.col.f32.bf16.bf16.f32 "
                 "{%0,%1,%2,%3}, {%4,%5,%6,%7}, {%8,%9}, {%0,%1,%2,%3};"
                 : "+f"(d[0]), "+f"(d[1]), "+f"(d[2]), "+f"(d[3])
                 : "r"(a[0]), "r"(a[1]), "r"(a[2]), "r"(a[3]), "r"(b0), "r"(b1));
}
__device__ __forceinline__ void fsplit(float v, float& hi, float& lo) {
    hi = __bfloat162float(__float2bfloat16_rn(v));
    lo = v - hi;
}
__device__ __forceinline__ uint32_t pk(float a, float b) {
    __nv_bfloat162 t;
    t.x = __float2bfloat16_rn(a);
    t.y = __float2bfloat16_rn(b);
    return *(uint32_t*)&t;
}
__device__ __forceinline__ float2 upk(uint32_t u) {
    __nv_bfloat162 t = *(__nv_bfloat162*)&u;
    return make_float2(__bfloat162float(t.x), __bfloat162float(t.y));
}

// ---------------- bf16x3 tensor-core GEMM ----------------
// C[M,N] = (Ah+Al)[M,256] @ (Bh+Bl)[N,256]^T   (both K-major)
// EPI 0: store. 1: += (Uh+Ul)*Dv. 2: += bias. 3: += bias, cols<ncols only.
#define SSTAGE 65536
#define OFF_AH 0
#define OFF_AL 16384
#define OFF_BH 32768
#define OFF_BL 49152
#define SM_GEMM (2 * SSTAGE)

template <int EPI>
__global__ void __launch_bounds__(256) tgemm(
    const __nv_bfloat16* __restrict__ Ah, const __nv_bfloat16* __restrict__ Al,
    const __nv_bfloat16* __restrict__ Bh, const __nv_bfloat16* __restrict__ Bl,
    const float* __restrict__ bias, float* __restrict__ C, int ldc, int ncols,
    const __nv_bfloat16* __restrict__ Uh, const __nv_bfloat16* __restrict__ Ul,
    const float* __restrict__ Dv) {
    extern __shared__ char smem[];
    uint32_t sb = smem_u32(smem);
    int tid = threadIdx.x, lane = tid & 31, wid = tid >> 5;
    int bm = blockIdx.y * 128, bn = blockIdx.x * 128;
    int Mw = (wid & 3) * 32, Nw = (wid >> 2) * 64;

    const int lrow = tid >> 3, lc16 = tid & 7;
    const uint32_t soff = ((uint32_t)lc16 << 4) ^ ((uint32_t)(lrow & 7) << 4);

    auto ldst = [&](int buf, int kc) {
        uint32_t sd = sb + buf * SSTAGE;
        const __nv_bfloat16* pa  = Ah + (size_t)(bm + lrow) * GK + kc + lc16 * 8;
        const __nv_bfloat16* pal = Al + (size_t)(bm + lrow) * GK + kc + lc16 * 8;
        const __nv_bfloat16* pb  = Bh + (size_t)(bn + lrow) * GK + kc + lc16 * 8;
        const __nv_bfloat16* pbl = Bl + (size_t)(bn + lrow) * GK + kc + lc16 * 8;
#pragma unroll
        for (int i = 0; i < 4; i++) {
            uint32_t so = (uint32_t)(lrow + 32 * i) * 128 + soff;
            cpa(sd + OFF_AH + so, pa  + (size_t)i * 32 * GK);
            cpa(sd + OFF_AL + so, pal + (size_t)i * 32 * GK);
            cpa(sd + OFF_BH + so, pb  + (size_t)i * 32 * GK);
            cpa(sd + OFF_BL + so, pbl + (size_t)i * 32 * GK);
        }
        asm volatile("cp.async.commit_group;" ::: "memory");
    };

    float acc[2][8][4] = {};
    uint32_t a_h[2][4], a_l[2][4], b_h[4][4], b_l[4][4];
    int ra = (lane & 7) + ((lane >> 3) & 1) * 8;
    int ca = (lane >> 4) << 4;
    int rb = (lane & 7) + ((lane >> 4) & 1) * 8;
    int cb = ((lane >> 3) & 1) << 4;

    ldst(0, 0);
    for (int c = 0; c < 4; c++) {
        if (c < 3) {
            ldst((c + 1) & 1, (c + 1) * 64);
            asm volatile("cp.async.wait_group 1;" ::: "memory");
        } else {
            asm volatile("cp.async.wait_group 0;" ::: "memory");
        }
        __syncthreads();
        uint32_t st = sb + (c & 1) * SSTAGE;
#pragma unroll
        for (int s = 0; s < 4; s++) {
#pragma unroll
            for (int mt = 0; mt < 2; mt++) {
                int r = Mw + mt * 16 + ra;
                uint32_t ad = st + (uint32_t)r * 128 + (((uint32_t)(s * 32 + ca)) ^ ((uint32_t)(r & 7) << 4));
                ldsm4(a_h[mt], ad + OFF_AH);
                ldsm4(a_l[mt], ad + OFF_AL);
            }
#pragma unroll
            for (int ng = 0; ng < 4; ng++) {
                int r = Nw + ng * 16 + rb;
                uint32_t ad = st + (uint32_t)r * 128 + (((uint32_t)(s * 32 + cb)) ^ ((uint32_t)(r & 7) << 4));
                ldsm4(b_h[ng], ad + OFF_BH);
                ldsm4(b_l[ng], ad + OFF_BL);
            }
#pragma unroll
            for (int mt = 0; mt < 2; mt++)
#pragma unroll
                for (int nf = 0; nf < 8; nf++) {
                    uint32_t bh0 = b_h[nf >> 1][(nf & 1) * 2], bh1 = b_h[nf >> 1][(nf & 1) * 2 + 1];
                    uint32_t bl0 = b_l[nf >> 1][(nf & 1) * 2], bl1 = b_l[nf >> 1][(nf & 1) * 2 + 1];
                    mma16816(acc[mt][nf], a_h[mt], bh0, bh1);
                    mma16816(acc[mt][nf], a_l[mt], bh0, bh1);
                    mma16816(acc[mt][nf], a_h[mt], bl0, bl1);
                }
        }
        __syncthreads();
    }

    // epilogue
#pragma unroll
    for (int mt = 0; mt < 2; mt++) {
        int r0 = bm + Mw + mt * 16 + (lane >> 2);
#pragma unroll
        for (int nf = 0; nf < 8; nf++) {
            int col = bn + Nw + nf * 8 + (lane & 3) * 2;
            float2 v0 = make_float2(acc[mt][nf][0], acc[mt][nf][1]);
            float2 v1 = make_float2(acc[mt][nf][2], acc[mt][nf][3]);
            if (EPI == 1) {
                float2 uh0 = upk(*(const uint32_t*)(Uh + (size_t)r0 * H + col));
                float2 ul0 = upk(*(const uint32_t*)(Ul + (size_t)r0 * H + col));
                float2 uh1 = upk(*(const uint32_t*)(Uh + (size_t)(r0 + 8) * H + col));
                float2 ul1 = upk(*(const uint32_t*)(Ul + (size_t)(r0 + 8) * H + col));
                float d0 = Dv[col], d1 = Dv[col + 1];
                v0.x += (uh0.x + ul0.x) * d0; v0.y += (uh0.y + ul0.y) * d1;
                v1.x += (uh1.x + ul1.x) * d0; v1.y += (uh1.y + ul1.y) * d1;
            }
            if (EPI >= 2) {
                float b0 = bias[col], b1 = bias[col + 1];
                v0.x += b0; v0.y += b1; v1.x += b0; v1.y += b1;
            }
            if (EPI != 3 || col < ncols) {
                *(float2*)(C + (size_t)r0 * ldc + col) = v0;
                *(float2*)(C + (size_t)(r0 + 8) * ldc + col) = v1;
            }
        }
    }
}

// ---------------- setup kernels ----------------
__global__ void k_x0(const float* __restrict__ latent, const float* __restrict__ W,
                     const float* __restrict__ b) {
    int j = threadIdx.x;
    float s = b[j];
    for (int i = 0; i < H; i++) s += latent[i] * W[i * H + j];
    g_x0[j] = s > 0.f ? s : 0.01f * s;
}

__global__ void k_fill() {
    int idx = blockIdx.x * blockDim.x + threadIdx.x;
    float4 v = ((const float4*)g_x0)[idx & 63];
    ((float4*)g_x)[idx] = v;
}

__global__ void k_prep(const float* __restrict__ Lre, const float* __restrict__ Lim,
                       const float* __restrict__ Bre, const float* __restrict__ Bim,
                       const float* __restrict__ Cre, const float* __restrict__ Cim,
                       const float* __restrict__ lstep) {
    int l = blockIdx.x >> 7;
    int p = blockIdx.x & 127;
    int h = threadIdx.x;
    float step = expf(lstep[l * PP + p]);
    float lr = Lre[l * PP + p], li = Lim[l * PP + p];
    float er = expf(lr * step);
    float sb, cb2;
    sincosf(li * step, &sb, &cb2);
    float abr = er * cb2, abi = er * sb;
    float den = lr * lr + li * li;
    float nr = abr - 1.f, ni = abi;
    float fr = (nr * lr + ni * li) / den;
    float fi = (ni * lr - nr * li) / den;
    float br = Bre[(l * PP + p) * H + h], bi = Bim[(l * PP + p) * H + h];
    float w0 = fr * br - fi * bi, w1 = fr * bi + fi * br;
    float hi, lo;
    int ib0 = l * H * H + (2 * p) * H + h, ib1 = l * H * H + (2 * p + 1) * H + h;
    fsplit(w0, hi, lo); g_Wbh[ib0] = __float2bfloat16_rn(hi); g_Wbl[ib0] = __float2bfloat16_rn(lo);
    fsplit(w1, hi, lo); g_Wbh[ib1] = __float2bfloat16_rn(hi); g_Wbl[ib1] = __float2bfloat16_rn(lo);
    float c0 = 2.f * Cre[(l * H + h) * PP + p], c1 = -2.f * Cim[(l * H + h) * PP + p];
    int ic0 = l * H * H + h * H + 2 * p, ic1 = ic0 + 1;
    fsplit(c0, hi, lo); g_Wch[ic0] = __float2bfloat16_rn(hi); g_Wcl[ic0] = __float2bfloat16_rn(lo);
    fsplit(c1, hi, lo); g_Wch[ic1] = __float2bfloat16_rn(hi); g_Wcl[ic1] = __float2bfloat16_rn(lo);
    if (h == 0) {
        g_abar[l * PP + p] = make_float2(abr, abi);
        float er2 = expf(lr * step * (float)CH);
        float sb2, cb3;
        sincosf(li * step * (float)CH, &sb2, &cb3);
        g_apow[l * PP + p] = make_float2(er2 * cb3, er2 * sb2);
    }
}

__global__ void k_wg(const float* __restrict__ W1, const float* __restrict__ b1,
                     const float* __restrict__ W2, const float* __restrict__ b2) {
    int idx = blockIdx.x * blockDim.x + threadIdx.x;  // NL*512*H
    int l = idx / (512 * H);
    int r = idx % (512 * H);
    int j = r / H, i = r % H;
    float w = (j < 256) ? W1[(l * H + i) * H + j] : W2[(l * H + i) * H + (j - 256)];
    float hi, lo;
    fsplit(w, hi, lo);
    g_Wgh[idx] = __float2bfloat16_rn(hi);
    g_Wgl[idx] = __float2bfloat16_rn(lo);
    if (i == 0) g_bg[l * 512 + j] = (j < 256) ? b1[l * H + j] : b2[l * H + (j - 256)];
}

__global__ void k_wout(const float* __restrict__ Wout, const float* __restrict__ bout) {
    int idx = blockIdx.x * blockDim.x + threadIdx.x;  // 128*H
    int j = idx / H, i = idx % H;
    float w = (j < 64) ? Wout[i * 64 + j] : 0.f;
    float hi, lo;
    fsplit(w, hi, lo);
    g_Woh[idx] = __float2bfloat16_rn(hi);
    g_Wol[idx] = __float2bfloat16_rn(lo);
    if (i == 0) g_boutP[j] = (j < 64) ? bout[j] : 0.f;
}

// ---------------- layernorm (+gelu), writes split bf16 ----------------
template <bool GELU>
__global__ void k_ln(const float* __restrict__ x, __nv_bfloat16* __restrict__ oh,
                     __nv_bfloat16* __restrict__ ol,
                     const float* __restrict__ sc, const float* __restrict__ bi) {
    int row = blockIdx.x * 4 + (threadIdx.x >> 5);
    int lane = threadIdx.x & 31;
    const float* xr = x + (size_t)row * H;
    float4 a = *(const float4*)(xr + lane * 8);
    float4 b = *(const float4*)(xr + lane * 8 + 4);
    float v[8] = {a.x, a.y, a.z, a.w, b.x, b.y, b.z, b.w};
    float s = 0.f, q = 0.f;
#pragma unroll
    for (int i = 0; i < 8; i++) { s += v[i]; q += v[i] * v[i]; }
#pragma unroll
    for (int off = 16; off; off >>= 1) {
        s += __shfl_xor_sync(0xffffffffu, s, off);
        q += __shfl_xor_sync(0xffffffffu, q, off);
    }
    float mu = s * (1.f / H);
    float var = q * (1.f / H) - mu * mu;
    float r = rsqrtf(var + 1e-6f);
    float out[8];
#pragma unroll
    for (int i = 0; i < 8; i++) {
        int col = lane * 8 + i;
        float t = (v[i] - mu) * r * sc[col] + bi[col];
        if (GELU) {
            float t3 = t * t * t;
            t = 0.5f * t * (1.f + tanhf(0.7978845608028654f * (t + 0.044715f * t3)));
        }
        out[i] = t;
    }
    uint32_t* oh32 = (uint32_t*)oh;
    uint32_t* ol32 = (uint32_t*)ol;
#pragma unroll
    for (int q2 = 0; q2 < 4; q2++) {
        float h0, l0, h1, l1;
        fsplit(out[2 * q2], h0, l0);
        fsplit(out[2 * q2 + 1], h1, l1);
        oh32[(size_t)row * 128 + lane * 4 + q2] = pk(h0, h1);
        ol32[(size_t)row * 128 + lane * 4 + q2] = pk(l0, l1);
    }
}

// ---------------- chunked diagonal complex scan ----------------
__global__ void k_scan1(int l) {
    int c = blockIdx.x, p = threadIdx.x;
    float2 a = g_abar[l * PP + p];
    const float2* bu = (const float2*)g_bu + (size_t)c * CH * PP + p;
    float2 st = make_float2(0.f, 0.f);
#pragma unroll 8
    for (int t = 0; t < CH; t++) {
        float2 b = bu[(size_t)t * PP];
        st = make_float2(a.x * st.x - a.y * st.y + b.x, a.x * st.y + a.y * st.x + b.y);
    }
    g_e[c * PP + p] = st;
}

__global__ void k_carry(int l) {
    int p = threadIdx.x;
    float2 ap = g_apow[l * PP + p];
    float2 cur = make_float2(0.f, 0.f);
    for (int c0 = 0; c0 < NCH; c0 += 8) {
        float2 e[8];
#pragma unroll
        for (int j = 0; j < 8; j++) e[j] = g_e[(c0 + j) * PP + p];
#pragma unroll
        for (int j = 0; j < 8; j++) {
            g_s[(c0 + j) * PP + p] = cur;
            cur = make_float2(ap.x * cur.x - ap.y * cur.y + e[j].x,
                              ap.x * cur.y + ap.y * cur.x + e[j].y);
        }
    }
}

__global__ void k_scan2(int l, __nv_bfloat16* __restrict__ sh, __nv_bfloat16* __restrict__ sl) {
    int c = blockIdx.x, p = threadIdx.x;
    float2 a = g_abar[l * PP + p];
    const float2* bu = (const float2*)g_bu + (size_t)c * CH * PP + p;
    uint32_t* sh32 = (uint32_t*)sh;
    uint32_t* sl32 = (uint32_t*)sl;
    float2 st = g_s[c * PP + p];
#pragma unroll 8
    for (int t = 0; t < CH; t++) {
        float2 b = bu[(size_t)t * PP];
        st = make_float2(a.x * st.x - a.y * st.y + b.x, a.x * st.y + a.y * st.x + b.y);
        float hr, lr2, hi2, li2;
        fsplit(st.x, hr, lr2);
        fsplit(st.y, hi2, li2);
        size_t row = (size_t)c * CH + t;
        sh32[row * 128 + p] = pk(hr, hi2);
        sl32[row * 128 + p] = pk(lr2, li2);
    }
}

// ---------------- GLU combine: x += p1 * sigmoid(p2) ----------------
__global__ void k_glu(int writeHL, __nv_bfloat16* __restrict__ sh, __nv_bfloat16* __restrict__ sl) {
    int idx = blockIdx.x * blockDim.x + threadIdx.x;  // L*H/4
    int row = idx >> 6;
    int c4 = idx & 63;
    float4 a = *(const float4*)(g_p + (size_t)row * 512 + c4 * 4);
    float4 b = *(const float4*)(g_p + (size_t)row * 512 + 256 + c4 * 4);
    float4 x = ((float4*)g_x)[idx];
    x.x += a.x * (1.f / (1.f + expf(-b.x)));
    x.y += a.y * (1.f / (1.f + expf(-b.y)));
    x.z += a.z * (1.f / (1.f + expf(-b.z)));
    x.w += a.w * (1.f / (1.f + expf(-b.w)));
    ((float4*)g_x)[idx] = x;
    if (writeHL) {
        float h0, l0, h1, l1, h2, l2, h3, l3;
        fsplit(x.x, h0, l0); fsplit(x.y, h1, l1);
        fsplit(x.z, h2, l2); fsplit(x.w, h3, l3);
        ((uint2*)sh)[(size_t)row * 64 + c4] = make_uint2(pk(h0, h1), pk(h2, h3));
        ((uint2*)sl)[(size_t)row * 64 + c4] = make_uint2(pk(l0, l1), pk(l2, l3));
    }
}

// ---------------- host launcher ----------------
extern "C" void kernel_launch(void* const* d_in, const int* in_sizes, int n_in,
                              void* d_out, int out_size) {
    const float* latent = (const float*)d_in[0];
    const float* Wexp   = (const float*)d_in[1];
    const float* bexp   = (const float*)d_in[2];
    const float* ns     = (const float*)d_in[3];
    const float* nb     = (const float*)d_in[4];
    const float* Lre    = (const float*)d_in[5];
    const float* Lim    = (const float*)d_in[6];
    const float* Bre    = (const float*)d_in[7];
    const float* Bim    = (const float*)d_in[8];
    const float* Cre    = (const float*)d_in[9];
    const float* Cim    = (const float*)d_in[10];
    const float* Dv     = (const float*)d_in[11];
    const float* lstep  = (const float*)d_in[12];
    const float* W1     = (const float*)d_in[13];
    const float* b1     = (const float*)d_in[14];
    const float* W2     = (const float*)d_in[15];
    const float* b2     = (const float*)d_in[16];
    const float* Wout   = (const float*)d_in[17];
    const float* bout   = (const float*)d_in[18];

    float *px, *pbu, *py, *pp, *pbg, *pboutP;
    __nv_bfloat16 *phh, *phl, *psh, *psl, *pWbh, *pWbl, *pWch, *pWcl, *pWgh, *pWgl, *pWoh, *pWol;
    cudaGetSymbolAddress((void**)&px, g_x);
    cudaGetSymbolAddress((void**)&pbu, g_bu);
    cudaGetSymbolAddress((void**)&py, g_y);
    cudaGetSymbolAddress((void**)&pp, g_p);
    cudaGetSymbolAddress((void**)&pbg, g_bg);
    cudaGetSymbolAddress((void**)&pboutP, g_boutP);
    cudaGetSymbolAddress((void**)&phh, g_hh);
    cudaGetSymbolAddress((void**)&phl, g_hl);
    cudaGetSymbolAddress((void**)&psh, g_sh);
    cudaGetSymbolAddress((void**)&psl, g_sl);
    cudaGetSymbolAddress((void**)&pWbh, g_Wbh);
    cudaGetSymbolAddress((void**)&pWbl, g_Wbl);
    cudaGetSymbolAddress((void**)&pWch, g_Wch);
    cudaGetSymbolAddress((void**)&pWcl, g_Wcl);
    cudaGetSymbolAddress((void**)&pWgh, g_Wgh);
    cudaGetSymbolAddress((void**)&pWgl, g_Wgl);
    cudaGetSymbolAddress((void**)&pWoh, g_Woh);
    cudaGetSymbolAddress((void**)&pWol, g_Wol);

    cudaFuncSetAttribute(tgemm<0>, cudaFuncAttributeMaxDynamicSharedMemorySize, SM_GEMM);
    cudaFuncSetAttribute(tgemm<1>, cudaFuncAttributeMaxDynamicSharedMemorySize, SM_GEMM);
    cudaFuncSetAttribute(tgemm<2>, cudaFuncAttributeMaxDynamicSharedMemorySize, SM_GEMM);
    cudaFuncSetAttribute(tgemm<3>, cudaFuncAttributeMaxDynamicSharedMemorySize, SM_GEMM);

    k_x0<<<1, 256>>>(latent, Wexp, bexp);
    k_fill<<<(LSEQ * H / 4) / 256, 256>>>();
    k_prep<<<NL * PP, 256>>>(Lre, Lim, Bre, Bim, Cre, Cim, lstep);
    k_wg<<<(NL * 512 * H) / 256, 256>>>(W1, b1, W2, b2);
    k_wout<<<(128 * H) / 256, 256>>>(Wout, bout);

    for (int l = 0; l < NL; l++) {
        k_ln<false><<<LSEQ / 4, 128>>>(px, phh, phl, ns + l * H, nb + l * H);
        tgemm<0><<<dim3(2, 256), 256, SM_GEMM>>>(phh, phl, pWbh + l * H * H, pWbl + l * H * H,
                                                 nullptr, pbu, H, H, nullptr, nullptr, nullptr);
        k_scan1<<<NCH, PP>>>(l);
        k_carry<<<1, PP>>>(l);
        k_scan2<<<NCH, PP>>>(l, psh, psl);
        tgemm<1><<<dim3(2, 256), 256, SM_GEMM>>>(psh, psl, pWch + l * H * H, pWcl + l * H * H,
                                                 nullptr, py, H, H, phh, phl, Dv + l * H);
        k_ln<true><<<LSEQ / 4, 128>>>(py, phh, phl, ns + l * H, nb + l * H);
        tgemm<2><<<dim3(4, 256), 256, SM_GEMM>>>(phh, phl, pWgh + l * 512 * H, pWgl + l * 512 * H,
                                                 pbg + l * 512, pp, 512, 512, nullptr, nullptr, nullptr);
        k_glu<<<(LSEQ * H / 4) / 256, 256>>>(l == NL - 1 ? 1 : 0, psh, psl);
    }
    tgemm<3><<<dim3(1, 256), 256, SM_GEMM>>>(psh, psl, pWoh, pWol, pboutP, (float*)d_out,
                                             64, 64, nullptr, nullptr, nullptr);
}

// round 8
// speedup vs baseline: 2.6145x; 1.0677x over previous
#include <cuda_runtime.h>
#include <cuda_bf16.h>
#include <cstdint>
#include <math.h>

#define LSEQ 32768
#define H 256
#define PP 128
#define CH 128
#define NCH 256
#define NL 4
#define GK 256

// ---------------- scratch (static __device__, no allocation) ----------------
__device__ float g_x[LSEQ * H];            // residual stream (fp32)
__device__ float g_bu[LSEQ * H];           // Bu, interleaved re/im (fp32)
__device__ float g_y[LSEQ * H];            // ssm output (fp32)
__device__ float g_p[LSEQ * 512];          // GLU pre-activations (fp32)
__device__ __nv_bfloat16 g_hh[LSEQ * H];   // ln/gelu output hi (also final x split hi)
__device__ __nv_bfloat16 g_hl[LSEQ * H];   // lo
__device__ __nv_bfloat16 g_sh[LSEQ * H];   // scan states hi
__device__ __nv_bfloat16 g_sl[LSEQ * H];   // scan states lo
__device__ float2 g_e[NCH * PP];
__device__ __nv_bfloat16 g_Wbh[NL * H * H], g_Wbl[NL * H * H];   // [N=2p][K=h]
__device__ __nv_bfloat16 g_Wch[NL * H * H], g_Wcl[NL * H * H];   // [N=h][K=2p]
__device__ __nv_bfloat16 g_Wgh[NL * 512 * H], g_Wgl[NL * 512 * H]; // [N=512][K=256]
__device__ float g_bg[NL * 512];
__device__ __nv_bfloat16 g_Woh[128 * H], g_Wol[128 * H];         // [N=128][K=256]
__device__ float g_boutP[128];
__device__ float2 g_abar[NL * PP];
__device__ float2 g_apow[NL * PP];
__device__ float g_x0[H];
__device__ __nv_bfloat16 g_h0h[H], g_h0l[H];

// ---------------- helpers ----------------
__device__ __forceinline__ uint32_t smem_u32(const void* p) {
    uint32_t a;
    asm("{ .reg .u64 t; cvta.to.shared.u64 t, %1; cvt.u32.u64 %0, t; }" : "=r"(a) : "l"(p));
    return a;
}
__device__ __forceinline__ void cpa(uint32_t s, const void* g) {
    asm volatile("cp.async.cg.shared.global [%0], [%1], 16;" :: "r"(s), "l"(g));
}
__device__ __forceinline__ void ldsm4(uint32_t* r, uint32_t a) {
    asm volatile("ldmatrix.sync.aligned.m8n8.x4.shared.b16 {%0,%1,%2,%3}, [%4];"
                 : "=r"(r[0]), "=r"(r[1]), "=r"(r[2]), "=r"(r[3]) : "r"(a));
}
__device__ __forceinline__ void mma16816(float* d, const uint32_t* a, uint32_t b0, uint32_t b1) {
    asm volatile("mma.sync.aligned.m16n8k16.row.col.f32.bf16.bf16.f32 "
                 "{%0,%1,%2,%3}, {%4,%5,%6,%7}, {%8,%9}, {%0,%1,%2,%3};"
                 : "+f"(d[0]), "+f"(d[1]), "+f"(d[2]), "+f"(d[3])
                 : "r"(a[0]), "r"(a[1]), "r"(a[2]), "r"(a[3]), "r"(b0), "r"(b1));
}
__device__ __forceinline__ void fsplit(float v, float& hi, float& lo) {
    hi = __bfloat162float(__float2bfloat16_rn(v));
    lo = v - hi;
}
__device__ __forceinline__ uint32_t pk(float a, float b) {
    __nv_bfloat162 t;
    t.x = __float2bfloat16_rn(a);
    t.y = __float2bfloat16_rn(b);
    return *(uint32_t*)&t;
}
__device__ __forceinline__ float2 upk(uint32_t u) {
    __nv_bfloat162 t = *(__nv_bfloat162*)&u;
    return make_float2(__bfloat162float(t.x), __bfloat162float(t.y));
}

// ---------------- bf16x3 tensor-core GEMM ----------------
#define SSTAGE 65536
#define OFF_AH 0
#define OFF_AL 16384
#define OFF_BH 32768
#define OFF_BL 49152
#define SM_GEMM (2 * SSTAGE)

template <int EPI>
__global__ void __launch_bounds__(256) tgemm(
    const __nv_bfloat16* __restrict__ Ah, const __nv_bfloat16* __restrict__ Al,
    const __nv_bfloat16* __restrict__ Bh, const __nv_bfloat16* __restrict__ Bl,
    const float* __restrict__ bias, float* __restrict__ C, int ldc, int ncols,
    const __nv_bfloat16* __restrict__ Uh, const __nv_bfloat16* __restrict__ Ul,
    const float* __restrict__ Dv) {
    extern __shared__ char smem[];
    uint32_t sb = smem_u32(smem);
    int tid = threadIdx.x, lane = tid & 31, wid = tid >> 5;
    int bm = blockIdx.y * 128, bn = blockIdx.x * 128;
    int Mw = (wid & 3) * 32, Nw = (wid >> 2) * 64;

    const int lrow = tid >> 3, lc16 = tid & 7;
    const uint32_t soff = ((uint32_t)lc16 << 4) ^ ((uint32_t)(lrow & 7) << 4);

    auto ldst = [&](int buf, int kc) {
        uint32_t sd = sb + buf * SSTAGE;
        const __nv_bfloat16* pa  = Ah + (size_t)(bm + lrow) * GK + kc + lc16 * 8;
        const __nv_bfloat16* pal = Al + (size_t)(bm + lrow) * GK + kc + lc16 * 8;
        const __nv_bfloat16* pb  = Bh + (size_t)(bn + lrow) * GK + kc + lc16 * 8;
        const __nv_bfloat16* pbl = Bl + (size_t)(bn + lrow) * GK + kc + lc16 * 8;
#pragma unroll
        for (int i = 0; i < 4; i++) {
            uint32_t so = (uint32_t)(lrow + 32 * i) * 128 + soff;
            cpa(sd + OFF_AH + so, pa  + (size_t)i * 32 * GK);
            cpa(sd + OFF_AL + so, pal + (size_t)i * 32 * GK);
            cpa(sd + OFF_BH + so, pb  + (size_t)i * 32 * GK);
            cpa(sd + OFF_BL + so, pbl + (size_t)i * 32 * GK);
        }
        asm volatile("cp.async.commit_group;" ::: "memory");
    };

    float acc[2][8][4] = {};
    uint32_t a_h[2][4], a_l[2][4], b_h[4][4], b_l[4][4];
    int ra = (lane & 7) + ((lane >> 3) & 1) * 8;
    int ca = (lane >> 4) << 4;
    int rb = (lane & 7) + ((lane >> 4) & 1) * 8;
    int cb = ((lane >> 3) & 1) << 4;

    ldst(0, 0);
    for (int c = 0; c < 4; c++) {
        if (c < 3) {
            ldst((c + 1) & 1, (c + 1) * 64);
            asm volatile("cp.async.wait_group 1;" ::: "memory");
        } else {
            asm volatile("cp.async.wait_group 0;" ::: "memory");
        }
        __syncthreads();
        uint32_t st = sb + (c & 1) * SSTAGE;
#pragma unroll
        for (int s = 0; s < 4; s++) {
#pragma unroll
            for (int mt = 0; mt < 2; mt++) {
                int r = Mw + mt * 16 + ra;
                uint32_t ad = st + (uint32_t)r * 128 + (((uint32_t)(s * 32 + ca)) ^ ((uint32_t)(r & 7) << 4));
                ldsm4(a_h[mt], ad + OFF_AH);
                ldsm4(a_l[mt], ad + OFF_AL);
            }
#pragma unroll
            for (int ng = 0; ng < 4; ng++) {
                int r = Nw + ng * 16 + rb;
                uint32_t ad = st + (uint32_t)r * 128 + (((uint32_t)(s * 32 + cb)) ^ ((uint32_t)(r & 7) << 4));
                ldsm4(b_h[ng], ad + OFF_BH);
                ldsm4(b_l[ng], ad + OFF_BL);
            }
#pragma unroll
            for (int mt = 0; mt < 2; mt++)
#pragma unroll
                for (int nf = 0; nf < 8; nf++) {
                    uint32_t bh0 = b_h[nf >> 1][(nf & 1) * 2], bh1 = b_h[nf >> 1][(nf & 1) * 2 + 1];
                    uint32_t bl0 = b_l[nf >> 1][(nf & 1) * 2], bl1 = b_l[nf >> 1][(nf & 1) * 2 + 1];
                    mma16816(acc[mt][nf], a_h[mt], bh0, bh1);
                    mma16816(acc[mt][nf], a_l[mt], bh0, bh1);
                    mma16816(acc[mt][nf], a_h[mt], bl0, bl1);
                }
        }
        __syncthreads();
    }

#pragma unroll
    for (int mt = 0; mt < 2; mt++) {
        int r0 = bm + Mw + mt * 16 + (lane >> 2);
#pragma unroll
        for (int nf = 0; nf < 8; nf++) {
            int col = bn + Nw + nf * 8 + (lane & 3) * 2;
            float2 v0 = make_float2(acc[mt][nf][0], acc[mt][nf][1]);
            float2 v1 = make_float2(acc[mt][nf][2], acc[mt][nf][3]);
            if (EPI == 1) {
                float2 uh0 = upk(*(const uint32_t*)(Uh + (size_t)r0 * H + col));
                float2 ul0 = upk(*(const uint32_t*)(Ul + (size_t)r0 * H + col));
                float2 uh1 = upk(*(const uint32_t*)(Uh + (size_t)(r0 + 8) * H + col));
                float2 ul1 = upk(*(const uint32_t*)(Ul + (size_t)(r0 + 8) * H + col));
                float d0 = Dv[col], d1 = Dv[col + 1];
                v0.x += (uh0.x + ul0.x) * d0; v0.y += (uh0.y + ul0.y) * d1;
                v1.x += (uh1.x + ul1.x) * d0; v1.y += (uh1.y + ul1.y) * d1;
            }
            if (EPI >= 2) {
                float b0 = bias[col], b1 = bias[col + 1];
                v0.x += b0; v0.y += b1; v1.x += b0; v1.y += b1;
            }
            if (EPI != 3 || col < ncols) {
                *(float2*)(C + (size_t)r0 * ldc + col) = v0;
                *(float2*)(C + (size_t)(r0 + 8) * ldc + col) = v1;
            }
        }
    }
}

// ---------------- k_x0: latent expand + leaky_relu + layer-0 LN (one row) ----------------
__global__ void k_x0(const float* __restrict__ latent, const float* __restrict__ W,
                     const float* __restrict__ b,
                     const float* __restrict__ sc, const float* __restrict__ bi) {
    int j = threadIdx.x;
    float s = b[j];
    for (int i = 0; i < H; i++) s += latent[i] * W[i * H + j];
    s = s > 0.f ? s : 0.01f * s;
    g_x0[j] = s;
    float sum = s, sq = s * s;
#pragma unroll
    for (int off = 16; off; off >>= 1) {
        sum += __shfl_xor_sync(0xffffffffu, sum, off);
        sq  += __shfl_xor_sync(0xffffffffu, sq, off);
    }
    __shared__ float ws[8], wq[8], mu_s, r_s;
    int w = j >> 5, lane = j & 31;
    if (lane == 0) { ws[w] = sum; wq[w] = sq; }
    __syncthreads();
    if (j == 0) {
        float S = 0.f, Q = 0.f;
        for (int k = 0; k < 8; k++) { S += ws[k]; Q += wq[k]; }
        float mu = S * (1.f / H);
        mu_s = mu;
        r_s = rsqrtf(Q * (1.f / H) - mu * mu + 1e-6f);
    }
    __syncthreads();
    float t = (s - mu_s) * r_s * sc[j] + bi[j];
    float hi, lo;
    fsplit(t, hi, lo);
    g_h0h[j] = __float2bfloat16_rn(hi);
    g_h0l[j] = __float2bfloat16_rn(lo);
}

// ---------------- k_fill: broadcast x0 and ln(x0) split to all rows ----------------
__global__ void k_fill() {
    int idx = blockIdx.x * blockDim.x + threadIdx.x;  // L*64
    int c = idx & 63;
    ((float4*)g_x)[idx] = ((const float4*)g_x0)[c];
    ((uint2*)g_hh)[idx] = ((const uint2*)g_h0h)[c];
    ((uint2*)g_hl)[idx] = ((const uint2*)g_h0l)[c];
}

// ---------------- k_setup: merged weight preprocessing ----------------
__global__ void k_setup(const float* __restrict__ Lre, const float* __restrict__ Lim,
                        const float* __restrict__ Bre, const float* __restrict__ Bim,
                        const float* __restrict__ Cre, const float* __restrict__ Cim,
                        const float* __restrict__ lstep,
                        const float* __restrict__ W1, const float* __restrict__ b1,
                        const float* __restrict__ W2, const float* __restrict__ b2,
                        const float* __restrict__ Wout, const float* __restrict__ bout) {
    int bb = blockIdx.x;
    float hi, lo;
    if (bb < NL * PP) {
        int l = bb >> 7, p = bb & 127, h = threadIdx.x;
        float step = expf(lstep[l * PP + p]);
        float lr = Lre[l * PP + p], li = Lim[l * PP + p];
        float er = expf(lr * step);
        float sb, cb2;
        sincosf(li * step, &sb, &cb2);
        float abr = er * cb2, abi = er * sb;
        float den = lr * lr + li * li;
        float nr = abr - 1.f, ni = abi;
        float fr = (nr * lr + ni * li) / den;
        float fi = (ni * lr - nr * li) / den;
        float br = Bre[(l * PP + p) * H + h], bi = Bim[(l * PP + p) * H + h];
        float w0 = fr * br - fi * bi, w1 = fr * bi + fi * br;
        int ib0 = l * H * H + (2 * p) * H + h, ib1 = l * H * H + (2 * p + 1) * H + h;
        fsplit(w0, hi, lo); g_Wbh[ib0] = __float2bfloat16_rn(hi); g_Wbl[ib0] = __float2bfloat16_rn(lo);
        fsplit(w1, hi, lo); g_Wbh[ib1] = __float2bfloat16_rn(hi); g_Wbl[ib1] = __float2bfloat16_rn(lo);
        float c0 = 2.f * Cre[(l * H + h) * PP + p], c1 = -2.f * Cim[(l * H + h) * PP + p];
        int ic0 = l * H * H + h * H + 2 * p, ic1 = ic0 + 1;
        fsplit(c0, hi, lo); g_Wch[ic0] = __float2bfloat16_rn(hi); g_Wcl[ic0] = __float2bfloat16_rn(lo);
        fsplit(c1, hi, lo); g_Wch[ic1] = __float2bfloat16_rn(hi); g_Wcl[ic1] = __float2bfloat16_rn(lo);
        if (h == 0) {
            g_abar[l * PP + p] = make_float2(abr, abi);
            float er2 = expf(lr * step * (float)CH);
            float sb2, cb3;
            sincosf(li * step * (float)CH, &sb2, &cb3);
            g_apow[l * PP + p] = make_float2(er2 * cb3, er2 * sb2);
        }
    } else if (bb < NL * PP + 2048) {
        int idx = (bb - NL * PP) * 256 + threadIdx.x;  // NL*512*H
        int l = idx / (512 * H);
        int r = idx % (512 * H);
        int j = r / H, i = r % H;
        float w = (j < 256) ? W1[(l * H + i) * H + j] : W2[(l * H + i) * H + (j - 256)];
        fsplit(w, hi, lo);
        g_Wgh[idx] = __float2bfloat16_rn(hi);
        g_Wgl[idx] = __float2bfloat16_rn(lo);
        if (i == 0) g_bg[l * 512 + j] = (j < 256) ? b1[l * H + j] : b2[l * H + (j - 256)];
    } else {
        int idx = (bb - NL * PP - 2048) * 256 + threadIdx.x;  // 128*H
        int j = idx / H, i = idx % H;
        float w = (j < 64) ? Wout[i * 64 + j] : 0.f;
        fsplit(w, hi, lo);
        g_Woh[idx] = __float2bfloat16_rn(hi);
        g_Wol[idx] = __float2bfloat16_rn(lo);
        if (i == 0) g_boutP[j] = (j < 64) ? bout[j] : 0.f;
    }
}

// ---------------- layernorm + gelu (post-SSM), writes split bf16 ----------------
__global__ void k_lng(const float* __restrict__ x, __nv_bfloat16* __restrict__ oh,
                      __nv_bfloat16* __restrict__ ol,
                      const float* __restrict__ sc, const float* __restrict__ bi) {
    int row = blockIdx.x * 4 + (threadIdx.x >> 5);
    int lane = threadIdx.x & 31;
    const float* xr = x + (size_t)row * H;
    float4 a = *(const float4*)(xr + lane * 8);
    float4 b = *(const float4*)(xr + lane * 8 + 4);
    float v[8] = {a.x, a.y, a.z, a.w, b.x, b.y, b.z, b.w};
    float s = 0.f, q = 0.f;
#pragma unroll
    for (int i = 0; i < 8; i++) { s += v[i]; q += v[i] * v[i]; }
#pragma unroll
    for (int off = 16; off; off >>= 1) {
        s += __shfl_xor_sync(0xffffffffu, s, off);
        q += __shfl_xor_sync(0xffffffffu, q, off);
    }
    float mu = s * (1.f / H);
    float var = q * (1.f / H) - mu * mu;
    float r = rsqrtf(var + 1e-6f);
    float out[8];
#pragma unroll
    for (int i = 0; i < 8; i++) {
        int col = lane * 8 + i;
        float t = (v[i] - mu) * r * sc[col] + bi[col];
        float t3 = t * t * t;
        t = 0.5f * t * (1.f + tanhf(0.7978845608028654f * (t + 0.044715f * t3)));
        out[i] = t;
    }
    uint32_t* oh32 = (uint32_t*)oh;
    uint32_t* ol32 = (uint32_t*)ol;
#pragma unroll
    for (int q2 = 0; q2 < 4; q2++) {
        float h0, l0, h1, l1;
        fsplit(out[2 * q2], h0, l0);
        fsplit(out[2 * q2 + 1], h1, l1);
        oh32[(size_t)row * 128 + lane * 4 + q2] = pk(h0, h1);
        ol32[(size_t)row * 128 + lane * 4 + q2] = pk(l0, l1);
    }
}

// ---------------- chunked diagonal complex scan ----------------
__global__ void k_scan1(int l) {
    int c = blockIdx.x, p = threadIdx.x;
    float2 a = g_abar[l * PP + p];
    const float2* bu = (const float2*)g_bu + (size_t)c * CH * PP + p;
    float2 st = make_float2(0.f, 0.f);
#pragma unroll 8
    for (int t = 0; t < CH; t++) {
        float2 b = bu[(size_t)t * PP];
        st = make_float2(a.x * st.x - a.y * st.y + b.x, a.x * st.y + a.y * st.x + b.y);
    }
    g_e[c * PP + p] = st;
}

// carry prefix fused into the second pass: each CTA self-computes its carry-in.
__global__ void k_scan2c(int l, __nv_bfloat16* __restrict__ sh, __nv_bfloat16* __restrict__ sl) {
    int c = blockIdx.x, p = threadIdx.x;
    float2 a = g_abar[l * PP + p];
    float2 ap = g_apow[l * PP + p];
    float2 st = make_float2(0.f, 0.f);
#pragma unroll 4
    for (int j = 0; j < c; j++) {
        float2 e = g_e[j * PP + p];
        st = make_float2(ap.x * st.x - ap.y * st.y + e.x, ap.x * st.y + ap.y * st.x + e.y);
    }
    const float2* bu = (const float2*)g_bu + (size_t)c * CH * PP + p;
    uint32_t* sh32 = (uint32_t*)sh;
    uint32_t* sl32 = (uint32_t*)sl;
#pragma unroll 8
    for (int t = 0; t < CH; t++) {
        float2 b = bu[(size_t)t * PP];
        st = make_float2(a.x * st.x - a.y * st.y + b.x, a.x * st.y + a.y * st.x + b.y);
        float hr, lr2, hi2, li2;
        fsplit(st.x, hr, lr2);
        fsplit(st.y, hi2, li2);
        size_t row = (size_t)c * CH + t;
        sh32[row * 128 + p] = pk(hr, hi2);
        sl32[row * 128 + p] = pk(lr2, li2);
    }
}

// ---------------- GLU combine fused with next-layer prenorm (or raw split) ----------------
template <bool RAW>
__global__ void __launch_bounds__(256) k_gluln(const float* __restrict__ sc,
                                               const float* __restrict__ bi) {
    int tid = threadIdx.x;
    int rb = tid >> 6, t = tid & 63;          // 4 rows/block, 64 threads/row
    int row = blockIdx.x * 4 + rb;
    const float* prow = g_p + (size_t)row * 512;
    float4 a = *(const float4*)(prow + t * 4);
    float4 b = *(const float4*)(prow + 256 + t * 4);
    float4 x = ((float4*)g_x)[(size_t)row * 64 + t];
    x.x += a.x * (1.f / (1.f + expf(-b.x)));
    x.y += a.y * (1.f / (1.f + expf(-b.y)));
    x.z += a.z * (1.f / (1.f + expf(-b.z)));
    x.w += a.w * (1.f / (1.f + expf(-b.w)));
    ((float4*)g_x)[(size_t)row * 64 + t] = x;
    float v[4] = {x.x, x.y, x.z, x.w};
    float out[4];
    if (!RAW) {
        float s = v[0] + v[1] + v[2] + v[3];
        float q = v[0] * v[0] + v[1] * v[1] + v[2] * v[2] + v[3] * v[3];
#pragma unroll
        for (int off = 16; off; off >>= 1) {
            s += __shfl_xor_sync(0xffffffffu, s, off);
            q += __shfl_xor_sync(0xffffffffu, q, off);
        }
        __shared__ float ws[8], wq[8];
        int w = tid >> 5, lane = tid & 31;
        if (lane == 0) { ws[w] = s; wq[w] = q; }
        __syncthreads();
        float S = ws[rb * 2] + ws[rb * 2 + 1];
        float Q = wq[rb * 2] + wq[rb * 2 + 1];
        float mu = S * (1.f / H);
        float r = rsqrtf(Q * (1.f / H) - mu * mu + 1e-6f);
#pragma unroll
        for (int i = 0; i < 4; i++)
            out[i] = (v[i] - mu) * r * sc[t * 4 + i] + bi[t * 4 + i];
    } else {
#pragma unroll
        for (int i = 0; i < 4; i++) out[i] = v[i];
    }
    float h0, l0, h1, l1, h2, l2, h3, l3;
    fsplit(out[0], h0, l0); fsplit(out[1], h1, l1);
    fsplit(out[2], h2, l2); fsplit(out[3], h3, l3);
    ((uint2*)g_hh)[(size_t)row * 64 + t] = make_uint2(pk(h0, h1), pk(h2, h3));
    ((uint2*)g_hl)[(size_t)row * 64 + t] = make_uint2(pk(l0, l1), pk(l2, l3));
}

// ---------------- host launcher ----------------
extern "C" void kernel_launch(void* const* d_in, const int* in_sizes, int n_in,
                              void* d_out, int out_size) {
    const float* latent = (const float*)d_in[0];
    const float* Wexp   = (const float*)d_in[1];
    const float* bexp   = (const float*)d_in[2];
    const float* ns     = (const float*)d_in[3];
    const float* nb     = (const float*)d_in[4];
    const float* Lre    = (const float*)d_in[5];
    const float* Lim    = (const float*)d_in[6];
    const float* Bre    = (const float*)d_in[7];
    const float* Bim    = (const float*)d_in[8];
    const float* Cre    = (const float*)d_in[9];
    const float* Cim    = (const float*)d_in[10];
    const float* Dv     = (const float*)d_in[11];
    const float* lstep  = (const float*)d_in[12];
    const float* W1     = (const float*)d_in[13];
    const float* b1     = (const float*)d_in[14];
    const float* W2     = (const float*)d_in[15];
    const float* b2     = (const float*)d_in[16];
    const float* Wout   = (const float*)d_in[17];
    const float* bout   = (const float*)d_in[18];

    float *pbu, *py, *pp, *pbg, *pboutP;
    __nv_bfloat16 *phh, *phl, *psh, *psl, *pWbh, *pWbl, *pWch, *pWcl, *pWgh, *pWgl, *pWoh, *pWol;
    cudaGetSymbolAddress((void**)&pbu, g_bu);
    cudaGetSymbolAddress((void**)&py, g_y);
    cudaGetSymbolAddress((void**)&pp, g_p);
    cudaGetSymbolAddress((void**)&pbg, g_bg);
    cudaGetSymbolAddress((void**)&pboutP, g_boutP);
    cudaGetSymbolAddress((void**)&phh, g_hh);
    cudaGetSymbolAddress((void**)&phl, g_hl);
    cudaGetSymbolAddress((void**)&psh, g_sh);
    cudaGetSymbolAddress((void**)&psl, g_sl);
    cudaGetSymbolAddress((void**)&pWbh, g_Wbh);
    cudaGetSymbolAddress((void**)&pWbl, g_Wbl);
    cudaGetSymbolAddress((void**)&pWch, g_Wch);
    cudaGetSymbolAddress((void**)&pWcl, g_Wcl);
    cudaGetSymbolAddress((void**)&pWgh, g_Wgh);
    cudaGetSymbolAddress((void**)&pWgl, g_Wgl);
    cudaGetSymbolAddress((void**)&pWoh, g_Woh);
    cudaGetSymbolAddress((void**)&pWol, g_Wol);

    cudaFuncSetAttribute(tgemm<0>, cudaFuncAttributeMaxDynamicSharedMemorySize, SM_GEMM);
    cudaFuncSetAttribute(tgemm<1>, cudaFuncAttributeMaxDynamicSharedMemorySize, SM_GEMM);
    cudaFuncSetAttribute(tgemm<2>, cudaFuncAttributeMaxDynamicSharedMemorySize, SM_GEMM);
    cudaFuncSetAttribute(tgemm<3>, cudaFuncAttributeMaxDynamicSharedMemorySize, SM_GEMM);

    k_x0<<<1, 256>>>(latent, Wexp, bexp, ns, nb);
    k_fill<<<(LSEQ * 64) / 256, 256>>>();
    k_setup<<<NL * PP + 2048 + 128, 256>>>(Lre, Lim, Bre, Bim, Cre, Cim, lstep,
                                           W1, b1, W2, b2, Wout, bout);

    for (int l = 0; l < NL; l++) {
        tgemm<0><<<dim3(2, 256), 256, SM_GEMM>>>(phh, phl, pWbh + l * H * H, pWbl + l * H * H,
                                                 nullptr, pbu, H, H, nullptr, nullptr, nullptr);
        k_scan1<<<NCH, PP>>>(l);
        k_scan2c<<<NCH, PP>>>(l, psh, psl);
        tgemm<1><<<dim3(2, 256), 256, SM_GEMM>>>(psh, psl, pWch + l * H * H, pWcl + l * H * H,
                                                 nullptr, py, H, H, phh, phl, Dv + l * H);
        k_lng<<<LSEQ / 4, 128>>>(py, phh, phl, ns + l * H, nb + l * H);
        tgemm<2><<<dim3(4, 256), 256, SM_GEMM>>>(phh, phl, pWgh + l * 512 * H, pWgl + l * 512 * H,
                                                 pbg + l * 512, pp, 512, 512, nullptr, nullptr, nullptr);
        if (l < NL - 1)
            k_gluln<false><<<LSEQ / 4, 256>>>(ns + (l + 1) * H, nb + (l + 1) * H);
        else
            k_gluln<true><<<LSEQ / 4, 256>>>(nullptr, nullptr);
    }
    tgemm<3><<<dim3(1, 256), 256, SM_GEMM>>>(phh, phl, pWoh, pWol, pboutP, (float*)d_out,
                                             64, 64, nullptr, nullptr, nullptr);
}